// round 4
// baseline (speedup 1.0000x reference)
#include <cuda_runtime.h>
#include <cstddef>

// ---------------------------------------------------------------------------
// StokenAttention: B=8, C=256, H=W=128, 8x8 super-tokens -> 16x16 grid,
// NH=8 heads, HD=KD=32.
// ---------------------------------------------------------------------------

#define Bb 8
#define Cc 256
#define GG 16
#define NT 256
#define NP 64
#define HW 16384
#define NH 8
#define HD 32
#define NTOK (Bb * NT)        // 2048 tokens total

__device__ float g_stoken[NTOK * Cc];            // [tok][c]
__device__ float g_aff[NTOK * NP * 9];           // [tok][p][k] packed 9
__device__ float g_asum[NTOK * 9];               // [tok][k]
__device__ float g_M[(size_t)NTOK * 9 * Cc];     // [tok][k][c]
__device__ float g_sf[NTOK * Cc];                // [tok][c]
__device__ float g_qkvt[(size_t)NTOK * 768];     // [tok][o]  (token-major!)
__device__ float g_tmp[NTOK * Cc];               // [tok][c]
__device__ float g_sfa[NTOK * Cc];               // [tok][c]

#define AFF_SCALE 0.0625f
#define ATTN_SCALE 0.17677669529663687f

// ------------------------------- K1: pooling -------------------------------
__global__ void k_pool(const float* __restrict__ x) {
    int bt = blockIdx.x;
    int t = bt & 255;
    int ty = t >> 4, tx = t & 15;
    int c = threadIdx.x;
    const float* xp = x + (size_t)(((bt >> 8) * Cc + c)) * HW + (ty * 8) * 128 + tx * 8;
    float s = 0.f;
#pragma unroll
    for (int i = 0; i < 8; i++) {
        float4 a = *(const float4*)(xp + i * 128);
        float4 b4 = *(const float4*)(xp + i * 128 + 4);
        s += a.x + a.y + a.z + a.w + b4.x + b4.y + b4.z + b4.w;
    }
    g_stoken[bt * Cc + c] = s * (1.0f / 64.0f);
}

// ------------------------- K2: affinity + token GEMM ------------------------
// smem: pix[64*257] | st9[9*256] | pd[8*64*9] | aff_s[64*12]
#define K2_PIX   (64 * 257)
#define K2_ST9   (9 * 256)
#define K2_PD    (8 * 64 * 9)
#define K2_AFFS  (64 * 12)
#define K2_SMEM  ((K2_PIX + K2_ST9 + K2_PD + K2_AFFS) * 4)

__global__ void k_aff(const float* __restrict__ x) {
    extern __shared__ float sm[];
    float* pix_s = sm;
    float* st9   = pix_s + K2_PIX;
    float* pd    = st9 + K2_ST9;
    float* aff_s = pd + K2_PD;

    int bt = blockIdx.x;
    int b = bt >> 8, t = bt & 255;
    int ty = t >> 4, tx = t & 15;
    int tid = threadIdx.x;

    for (int idx = tid; idx < 9 * Cc; idx += 256) {
        int k = idx >> 8, c = idx & 255;
        int ny = ty + k / 3 - 1, nx = tx + k % 3 - 1;
        float v = 0.f;
        if ((unsigned)ny < GG && (unsigned)nx < GG)
            v = g_stoken[(b * NT + ny * GG + nx) * Cc + c];
        st9[idx] = v;
    }
    const float* xb = x + (size_t)b * Cc * HW + (ty * 8) * 128 + tx * 8;
    for (int idx = tid; idx < NP * Cc; idx += 256) {
        int c = idx >> 6;
        int p = idx & 63;
        int sy = p >> 3, sx = p & 7;
        pix_s[p * 257 + c] = xb[(size_t)c * HW + sy * 128 + sx];
    }
    __syncthreads();

    // dot products: thread = (p-pair, c-eighth)
    {
        int p2 = tid & 31, q = tid >> 5;        // q in 0..7
        const float* pr0 = pix_s + (2 * p2) * 257 + q * 32;
        const float* pr1 = pr0 + 257;
        const float* sr  = st9 + q * 32;
        float a0[9], a1[9];
#pragma unroll
        for (int k = 0; k < 9; k++) { a0[k] = 0.f; a1[k] = 0.f; }
#pragma unroll 8
        for (int cc = 0; cc < 32; cc++) {
            float v0 = pr0[cc], v1 = pr1[cc];
#pragma unroll
            for (int k = 0; k < 9; k++) {
                float sv = sr[k * 256 + cc];
                a0[k] += v0 * sv;
                a1[k] += v1 * sv;
            }
        }
        float* o0 = pd + (q * 64 + 2 * p2) * 9;
#pragma unroll
        for (int k = 0; k < 9; k++) { o0[k] = a0[k]; o0[9 + k] = a1[k]; }
    }
    __syncthreads();
    for (int idx = tid; idx < 576; idx += 256) {
        float s = 0.f;
#pragma unroll
        for (int j = 0; j < 8; j++) s += pd[j * 576 + idx];
        int p = idx / 9, k = idx - p * 9;
        aff_s[p * 12 + k] = s * AFF_SCALE;
    }
    __syncthreads();
    if (tid < 64) {
        float v[9];
        float mx = -1e30f;
#pragma unroll
        for (int k = 0; k < 9; k++) { v[k] = aff_s[tid * 12 + k]; mx = fmaxf(mx, v[k]); }
        float sum = 0.f;
#pragma unroll
        for (int k = 0; k < 9; k++) { v[k] = __expf(v[k] - mx); sum += v[k]; }
        float inv = 1.f / sum;
#pragma unroll
        for (int k = 0; k < 9; k++) aff_s[tid * 12 + k] = v[k] * inv;
    }
    __syncthreads();
    for (int idx = tid; idx < 576; idx += 256) {
        int p = idx / 9, k = idx - p * 9;
        g_aff[bt * 576 + idx] = aff_s[p * 12 + k];
    }
    if (tid < 9) {
        float s = 0.f;
        for (int p = 0; p < 64; p++) s += aff_s[p * 12 + tid];
        g_asum[bt * 9 + tid] = s;
    }
    // token GEMM: M[k][c] = sum_p pix[p][c]*aff[p][k]
    {
        int c = tid;
        float acc[9];
#pragma unroll
        for (int k = 0; k < 9; k++) acc[k] = 0.f;
#pragma unroll 8
        for (int p = 0; p < 64; p++) {
            float pv = pix_s[p * 257 + c];
            float4 afa = *(const float4*)&aff_s[p * 12];
            float4 afb = *(const float4*)&aff_s[p * 12 + 4];
            float af8 = aff_s[p * 12 + 8];
            acc[0] += pv * afa.x; acc[1] += pv * afa.y;
            acc[2] += pv * afa.z; acc[3] += pv * afa.w;
            acc[4] += pv * afb.x; acc[5] += pv * afb.y;
            acc[6] += pv * afb.z; acc[7] += pv * afb.w;
            acc[8] += pv * af8;
        }
        float* Mo = g_M + (size_t)bt * 9 * Cc;
#pragma unroll
        for (int k = 0; k < 9; k++) Mo[k * Cc + c] = acc[k];
    }
}

// ------------------------------- K3: fold ----------------------------------
__global__ void k_fold() {
    int bt = blockIdx.x;
    int b = bt >> 8, t = bt & 255;
    int y = t >> 4, x = t & 15;
    __shared__ float s_as;
    int tid = threadIdx.x;
    if (tid == 0) {
        float s = 0.f;
        for (int ny = y - 1; ny <= y + 1; ny++)
            for (int nx = x - 1; nx <= x + 1; nx++)
                if ((unsigned)ny < GG && (unsigned)nx < GG) {
                    int k = (y - ny + 1) * 3 + (x - nx + 1);
                    s += g_asum[(b * NT + ny * GG + nx) * 9 + k];
                }
        s_as = s + 1e-12f;
    }
    __syncthreads();
    int c = tid;
    float s = 0.f;
    for (int ny = y - 1; ny <= y + 1; ny++)
        for (int nx = x - 1; nx <= x + 1; nx++)
            if ((unsigned)ny < GG && (unsigned)nx < GG) {
                int k = (y - ny + 1) * 3 + (x - nx + 1);
                s += g_M[((size_t)(b * NT + ny * GG + nx) * 9 + k) * Cc + c];
            }
    g_sf[bt * Cc + c] = s / s_as;
}

// --------------------------- GEMM (token-major out) -------------------------
// C[n][m] = sum_k A[m][k] * Bm[n][k];  K=256 fixed; tile 64x64, micro 4x4,
// k-major smem frags (2x LDS.128 per 16 FFMA), double-buffered.
template <int MM>
__device__ __forceinline__ void gemm_tok(const float* __restrict__ A,
                                         const float* __restrict__ Bm,
                                         float* __restrict__ Cm) {
    const int K = 256;
    __shared__ float As[2][32 * 68];
    __shared__ float Bs[2][32 * 68];
    int bm = blockIdx.x * 64;
    int bn = blockIdx.y * 64;
    int tid = threadIdx.x;
    int txq = tid & 15, tyq = tid >> 4;

    float4 rA[2], rB[2];
    int f0 = tid, f1 = tid + 256;
    int r0 = f0 >> 3, k0q = (f0 & 7) * 4;
    int r1 = f1 >> 3, k1q = (f1 & 7) * 4;

    // prologue load tile 0
    rA[0] = *(const float4*)(A + (size_t)(bm + r0) * K + k0q);
    rA[1] = *(const float4*)(A + (size_t)(bm + r1) * K + k1q);
    rB[0] = *(const float4*)(Bm + (size_t)(bn + r0) * K + k0q);
    rB[1] = *(const float4*)(Bm + (size_t)(bn + r1) * K + k1q);
    As[0][(k0q + 0) * 68 + r0] = rA[0].x; As[0][(k0q + 1) * 68 + r0] = rA[0].y;
    As[0][(k0q + 2) * 68 + r0] = rA[0].z; As[0][(k0q + 3) * 68 + r0] = rA[0].w;
    As[0][(k1q + 0) * 68 + r1] = rA[1].x; As[0][(k1q + 1) * 68 + r1] = rA[1].y;
    As[0][(k1q + 2) * 68 + r1] = rA[1].z; As[0][(k1q + 3) * 68 + r1] = rA[1].w;
    Bs[0][(k0q + 0) * 68 + r0] = rB[0].x; Bs[0][(k0q + 1) * 68 + r0] = rB[0].y;
    Bs[0][(k0q + 2) * 68 + r0] = rB[0].z; Bs[0][(k0q + 3) * 68 + r0] = rB[0].w;
    Bs[0][(k1q + 0) * 68 + r1] = rB[1].x; Bs[0][(k1q + 1) * 68 + r1] = rB[1].y;
    Bs[0][(k1q + 2) * 68 + r1] = rB[1].z; Bs[0][(k1q + 3) * 68 + r1] = rB[1].w;
    __syncthreads();

    float acc[4][4];
#pragma unroll
    for (int i = 0; i < 4; i++)
#pragma unroll
        for (int j = 0; j < 4; j++) acc[i][j] = 0.f;

#pragma unroll
    for (int tile = 0; tile < 8; tile++) {
        if (tile < 7) {
            int kb = (tile + 1) * 32;
            rA[0] = *(const float4*)(A + (size_t)(bm + r0) * K + kb + k0q);
            rA[1] = *(const float4*)(A + (size_t)(bm + r1) * K + kb + k1q);
            rB[0] = *(const float4*)(Bm + (size_t)(bn + r0) * K + kb + k0q);
            rB[1] = *(const float4*)(Bm + (size_t)(bn + r1) * K + kb + k1q);
        }
        int buf = tile & 1;
#pragma unroll
        for (int kk = 0; kk < 32; kk++) {
            float4 a = *(const float4*)&As[buf][kk * 68 + tyq * 4];
            float4 bb = *(const float4*)&Bs[buf][kk * 68 + txq * 4];
            acc[0][0] += a.x * bb.x; acc[0][1] += a.x * bb.y;
            acc[0][2] += a.x * bb.z; acc[0][3] += a.x * bb.w;
            acc[1][0] += a.y * bb.x; acc[1][1] += a.y * bb.y;
            acc[1][2] += a.y * bb.z; acc[1][3] += a.y * bb.w;
            acc[2][0] += a.z * bb.x; acc[2][1] += a.z * bb.y;
            acc[2][2] += a.z * bb.z; acc[2][3] += a.z * bb.w;
            acc[3][0] += a.w * bb.x; acc[3][1] += a.w * bb.y;
            acc[3][2] += a.w * bb.z; acc[3][3] += a.w * bb.w;
        }
        if (tile < 7) {
            int nb = (tile + 1) & 1;
            As[nb][(k0q + 0) * 68 + r0] = rA[0].x; As[nb][(k0q + 1) * 68 + r0] = rA[0].y;
            As[nb][(k0q + 2) * 68 + r0] = rA[0].z; As[nb][(k0q + 3) * 68 + r0] = rA[0].w;
            As[nb][(k1q + 0) * 68 + r1] = rA[1].x; As[nb][(k1q + 1) * 68 + r1] = rA[1].y;
            As[nb][(k1q + 2) * 68 + r1] = rA[1].z; As[nb][(k1q + 3) * 68 + r1] = rA[1].w;
            Bs[nb][(k0q + 0) * 68 + r0] = rB[0].x; Bs[nb][(k0q + 1) * 68 + r0] = rB[0].y;
            Bs[nb][(k0q + 2) * 68 + r0] = rB[0].z; Bs[nb][(k0q + 3) * 68 + r0] = rB[0].w;
            Bs[nb][(k1q + 0) * 68 + r1] = rB[1].x; Bs[nb][(k1q + 1) * 68 + r1] = rB[1].y;
            Bs[nb][(k1q + 2) * 68 + r1] = rB[1].z; Bs[nb][(k1q + 3) * 68 + r1] = rB[1].w;
            __syncthreads();
        }
    }
    // write C[n][m], vectorized along m
#pragma unroll
    for (int j = 0; j < 4; j++) {
        float4 v;
        v.x = acc[0][j]; v.y = acc[1][j]; v.z = acc[2][j]; v.w = acc[3][j];
        *(float4*)(Cm + (size_t)(bn + txq * 4 + j) * MM + bm + tyq * 4) = v;
    }
}

__global__ void k_gemm_qkv(const float* __restrict__ A) { gemm_tok<768>(A, g_sf, g_qkvt); }
__global__ void k_gemm_proj(const float* __restrict__ A) { gemm_tok<256>(A, g_tmp, g_sfa); }

// ------------------------------ K5: attention -------------------------------
// 128 blocks = b(8) x h(8) x qhalf(2); 128 threads, thread = one query.
// K/V staged [m][36] (8 float4 + pad) for broadcast LDS.128. Chunked online
// softmax (chunk=8). Depthwise 3x3 PE fused; writes token-major g_tmp.
#define K5_KV   (256 * 36)
#define K5_SMEM ((2 * K5_KV + 9 * 32) * 4)

__global__ void k_attn(const float* __restrict__ w_pe) {
    extern __shared__ float sm5[];
    float* k_s = sm5;
    float* v_s = k_s + K5_KV;
    float* wpe = v_s + K5_KV;   // [k][d] 9x32

    int bx = blockIdx.x;
    int b = bx >> 4;
    int h = (bx >> 1) & 7;
    int qh = bx & 1;
    int tid = threadIdx.x;

    const float* base = g_qkvt + (size_t)b * NT * 768 + h * 96;
    // fill K/V: coalesced float4 reads (token-major qkvt), STS.128
#pragma unroll
    for (int i = 0; i < 16; i++) {
        int f = tid + i * 128;
        int m = f >> 3, dq = (f & 7) * 4;
        float4 kv = *(const float4*)(base + (size_t)m * 768 + 32 + dq);
        float4 vv = *(const float4*)(base + (size_t)m * 768 + 64 + dq);
        *(float4*)&k_s[m * 36 + dq] = kv;
        *(float4*)&v_s[m * 36 + dq] = vv;
    }
    for (int idx = tid; idx < 288; idx += 128) {
        int d = idx & 31, k = idx >> 5;
        wpe[k * 32 + d] = w_pe[(h * 32 + d) * 9 + k];
    }
    __syncthreads();

    int j = qh * 128 + tid;
    float q[32];
#pragma unroll
    for (int i = 0; i < 8; i++) {
        float4 qv = *(const float4*)(base + (size_t)j * 768 + i * 4);
        q[4 * i + 0] = qv.x * ATTN_SCALE; q[4 * i + 1] = qv.y * ATTN_SCALE;
        q[4 * i + 2] = qv.z * ATTN_SCALE; q[4 * i + 3] = qv.w * ATTN_SCALE;
    }

    float o[32];
#pragma unroll
    for (int d = 0; d < 32; d++) o[d] = 0.f;
    float mx = -1e30f, l = 0.f;

    for (int m0 = 0; m0 < 256; m0 += 8) {
        float sc[8];
        float cmax = -1e30f;
#pragma unroll
        for (int mm = 0; mm < 8; mm++) {
            const float* kr = k_s + (m0 + mm) * 36;
            float s = 0.f;
#pragma unroll
            for (int i = 0; i < 8; i++) {
                float4 kv = *(const float4*)(kr + 4 * i);
                s += q[4 * i + 0] * kv.x + q[4 * i + 1] * kv.y
                   + q[4 * i + 2] * kv.z + q[4 * i + 3] * kv.w;
            }
            sc[mm] = s;
            cmax = fmaxf(cmax, s);
        }
        float nm = fmaxf(mx, cmax);
        float corr = __expf(mx - nm);
        l *= corr;
#pragma unroll
        for (int d = 0; d < 32; d++) o[d] *= corr;
#pragma unroll
        for (int mm = 0; mm < 8; mm++) {
            float p = __expf(sc[mm] - nm);
            l += p;
            const float* vr = v_s + (m0 + mm) * 36;
#pragma unroll
            for (int i = 0; i < 8; i++) {
                float4 vv = *(const float4*)(vr + 4 * i);
                o[4 * i + 0] += p * vv.x; o[4 * i + 1] += p * vv.y;
                o[4 * i + 2] += p * vv.z; o[4 * i + 3] += p * vv.w;
            }
        }
        mx = nm;
    }
    float invl = 1.f / l;

    // depthwise 3x3 PE on v + output
    int y = j >> 4, xx = j & 15;
    float* outp = g_tmp + ((size_t)(b * NT + j)) * Cc + h * 32;
#pragma unroll
    for (int i = 0; i < 8; i++) {
        float pe0 = 0.f, pe1 = 0.f, pe2 = 0.f, pe3 = 0.f;
#pragma unroll
        for (int u = 0; u < 3; u++) {
            int ny = y + u - 1;
            if ((unsigned)ny >= GG) continue;
#pragma unroll
            for (int v = 0; v < 3; v++) {
                int nx = xx + v - 1;
                if ((unsigned)nx >= GG) continue;
                int k = u * 3 + v;
                float4 w4 = *(const float4*)&wpe[k * 32 + 4 * i];
                float4 vv = *(const float4*)&v_s[(ny * 16 + nx) * 36 + 4 * i];
                pe0 += w4.x * vv.x; pe1 += w4.y * vv.y;
                pe2 += w4.z * vv.z; pe3 += w4.w * vv.w;
            }
        }
        float4 r;
        r.x = o[4 * i + 0] * invl + pe0;
        r.y = o[4 * i + 1] * invl + pe1;
        r.z = o[4 * i + 2] * invl + pe2;
        r.w = o[4 * i + 3] * invl + pe3;
        *(float4*)(outp + 4 * i) = r;
    }
}

// ------------------------------ K7: scatter ---------------------------------
// out[c][s] = sum_k aff[c>>2][k] * sfa9[k][(c&3)*64 + s]. Thread = channel c;
// float4 over s (broadcast aff in regs, broadcast-group s9 LDS.128, STG.128).
__global__ void k_scatter(float* __restrict__ out) {
    __shared__ float s9[9 * 256];        // [k][ch]
    __shared__ float aff_s[64 * 12];     // [p][k] padded
    int bt = blockIdx.x;
    int b = bt >> 8, t = bt & 255;
    int ty = t >> 4, tx = t & 15;
    int tid = threadIdx.x;

    for (int idx = tid; idx < 9 * 256; idx += 256) {
        int k = idx >> 8, c = idx & 255;
        int ny = ty + k / 3 - 1, nx = tx + k % 3 - 1;
        s9[idx] = ((unsigned)ny < GG && (unsigned)nx < GG)
                      ? g_sfa[(size_t)(b * NT + ny * GG + nx) * Cc + c]
                      : 0.f;
    }
    for (int idx = tid; idx < 576; idx += 256) {
        int p = idx / 9, k = idx - p * 9;
        aff_s[p * 12 + k] = g_aff[bt * 576 + idx];
    }
    __syncthreads();

    int c = tid;
    int p = c >> 2, cq = c & 3;
    float a[9];
#pragma unroll
    for (int k = 0; k < 9; k++) a[k] = aff_s[p * 12 + k];
    float* op = out + (size_t)b * Cc * HW + (size_t)c * HW + (ty * 8) * 128 + tx * 8;
#pragma unroll
    for (int s4 = 0; s4 < 16; s4++) {
        int sy = s4 >> 1, sxb = (s4 & 1) * 4;
        float4 acc; acc.x = 0.f; acc.y = 0.f; acc.z = 0.f; acc.w = 0.f;
#pragma unroll
        for (int k = 0; k < 9; k++) {
            float4 v = *(const float4*)&s9[k * 256 + cq * 64 + s4 * 4];
            acc.x += a[k] * v.x; acc.y += a[k] * v.y;
            acc.z += a[k] * v.z; acc.w += a[k] * v.w;
        }
        *(float4*)(op + sy * 128 + sxb) = acc;
    }
}

// ------------------------------- launcher -----------------------------------
extern "C" void kernel_launch(void* const* d_in, const int* in_sizes, int n_in,
                              void* d_out, int out_size) {
    (void)in_sizes; (void)n_in; (void)out_size;
    const float* x      = (const float*)d_in[0];
    const float* w_qkv  = (const float*)d_in[1];
    const float* w_pe   = (const float*)d_in[2];
    const float* w_proj = (const float*)d_in[3];
    float* out = (float*)d_out;

    cudaFuncSetAttribute(k_aff, cudaFuncAttributeMaxDynamicSharedMemorySize, K2_SMEM);
    cudaFuncSetAttribute(k_attn, cudaFuncAttributeMaxDynamicSharedMemorySize, K5_SMEM);

    k_pool<<<NTOK, 256>>>(x);
    k_aff<<<NTOK, 256, K2_SMEM>>>(x);
    k_fold<<<NTOK, 256>>>();
    k_gemm_qkv<<<dim3(12, 32), 256>>>(w_qkv);
    k_attn<<<128, 128, K5_SMEM>>>(w_pe);
    k_gemm_proj<<<dim3(4, 32), 256>>>(w_proj);
    k_scatter<<<NTOK, 256>>>(out);
}

// round 5
// speedup vs baseline: 1.4135x; 1.4135x over previous
#include <cuda_runtime.h>
#include <cstddef>

// ---------------------------------------------------------------------------
// StokenAttention: B=8, C=256, H=W=128, 8x8 super-tokens -> 16x16 grid,
// NH=8 heads, HD=KD=32.
// ---------------------------------------------------------------------------

#define Bb 8
#define Cc 256
#define GG 16
#define NT 256
#define NP 64
#define HW 16384
#define NH 8
#define HD 32
#define NTOK (Bb * NT)        // 2048 tokens total

__device__ float g_stoken[NTOK * Cc];            // [tok][c]
__device__ float g_aff[NTOK * NP * 9];           // [tok][p][k] packed 9
__device__ float g_asum[NTOK * 9];               // [tok][k]
__device__ float g_M[(size_t)NTOK * 9 * Cc];     // [tok][k][c]
__device__ float g_sf[NTOK * Cc];                // [tok][c]
__device__ float g_qkvt[(size_t)NTOK * 768];     // [tok][o]  (token-major)
__device__ float g_tmp[NTOK * Cc];               // [tok][c]
__device__ float g_sfa[NTOK * Cc];               // [tok][c]

#define AFF_SCALE 0.0625f
#define ATTN_SCALE 0.17677669529663687f

// ------------------------------- K1: pooling -------------------------------
__global__ void k_pool(const float* __restrict__ x) {
    int bt = blockIdx.x;
    int t = bt & 255;
    int ty = t >> 4, tx = t & 15;
    int c = threadIdx.x;
    const float* xp = x + (size_t)(((bt >> 8) * Cc + c)) * HW + (ty * 8) * 128 + tx * 8;
    float s = 0.f;
#pragma unroll
    for (int i = 0; i < 8; i++) {
        float4 a = *(const float4*)(xp + i * 128);
        float4 b4 = *(const float4*)(xp + i * 128 + 4);
        s += a.x + a.y + a.z + a.w + b4.x + b4.y + b4.z + b4.w;
    }
    g_stoken[bt * Cc + c] = s * (1.0f / 64.0f);
}

// ------------------------- K2: affinity + token GEMM ------------------------
// smem: pix[64*257] | st9[9*256] | pd[8*64*9] | aff_s[64*12]
#define K2_PIX   (64 * 257)
#define K2_ST9   (9 * 256)
#define K2_PD    (8 * 64 * 9)
#define K2_AFFS  (64 * 12)
#define K2_SMEM  ((K2_PIX + K2_ST9 + K2_PD + K2_AFFS) * 4)

__global__ void k_aff(const float* __restrict__ x) {
    extern __shared__ float sm[];
    float* pix_s = sm;
    float* st9   = pix_s + K2_PIX;
    float* pd    = st9 + K2_ST9;
    float* aff_s = pd + K2_PD;

    int bt = blockIdx.x;
    int b = bt >> 8, t = bt & 255;
    int ty = t >> 4, tx = t & 15;
    int tid = threadIdx.x;

    for (int idx = tid; idx < 9 * Cc; idx += 256) {
        int k = idx >> 8, c = idx & 255;
        int ny = ty + k / 3 - 1, nx = tx + k % 3 - 1;
        float v = 0.f;
        if ((unsigned)ny < GG && (unsigned)nx < GG)
            v = g_stoken[(b * NT + ny * GG + nx) * Cc + c];
        st9[idx] = v;
    }
    const float* xb = x + (size_t)b * Cc * HW + (ty * 8) * 128 + tx * 8;
    for (int idx = tid; idx < NP * Cc; idx += 256) {
        int c = idx >> 6;
        int p = idx & 63;
        int sy = p >> 3, sx = p & 7;
        pix_s[p * 257 + c] = xb[(size_t)c * HW + sy * 128 + sx];
    }
    __syncthreads();

    // dot products: thread = (p, p+32, c-eighth); lane bank-stride 257 (no conflicts)
    {
        int p2 = tid & 31, q = tid >> 5;        // q in 0..7
        const float* pr0 = pix_s + p2 * 257 + q * 32;
        const float* pr1 = pix_s + (p2 + 32) * 257 + q * 32;
        const float* sr  = st9 + q * 32;
        float a0[9], a1[9];
#pragma unroll
        for (int k = 0; k < 9; k++) { a0[k] = 0.f; a1[k] = 0.f; }
#pragma unroll 8
        for (int cc = 0; cc < 32; cc++) {
            float v0 = pr0[cc], v1 = pr1[cc];
#pragma unroll
            for (int k = 0; k < 9; k++) {
                float sv = sr[k * 256 + cc];
                a0[k] += v0 * sv;
                a1[k] += v1 * sv;
            }
        }
        float* o0 = pd + (q * 64 + p2) * 9;
        float* o1 = pd + (q * 64 + p2 + 32) * 9;
#pragma unroll
        for (int k = 0; k < 9; k++) { o0[k] = a0[k]; o1[k] = a1[k]; }
    }
    __syncthreads();
    for (int idx = tid; idx < 576; idx += 256) {
        float s = 0.f;
#pragma unroll
        for (int j = 0; j < 8; j++) s += pd[j * 576 + idx];
        int p = idx / 9, k = idx - p * 9;
        aff_s[p * 12 + k] = s * AFF_SCALE;
    }
    __syncthreads();
    if (tid < 64) {
        float v[9];
        float mx = -1e30f;
#pragma unroll
        for (int k = 0; k < 9; k++) { v[k] = aff_s[tid * 12 + k]; mx = fmaxf(mx, v[k]); }
        float sum = 0.f;
#pragma unroll
        for (int k = 0; k < 9; k++) { v[k] = __expf(v[k] - mx); sum += v[k]; }
        float inv = 1.f / sum;
#pragma unroll
        for (int k = 0; k < 9; k++) aff_s[tid * 12 + k] = v[k] * inv;
    }
    __syncthreads();
    for (int idx = tid; idx < 576; idx += 256) {
        int p = idx / 9, k = idx - p * 9;
        g_aff[bt * 576 + idx] = aff_s[p * 12 + k];
    }
    if (tid < 9) {
        float s = 0.f;
        for (int p = 0; p < 64; p++) s += aff_s[p * 12 + tid];
        g_asum[bt * 9 + tid] = s;
    }
    // token GEMM: M[k][c] = sum_p pix[p][c]*aff[p][k]
    {
        int c = tid;
        float acc[9];
#pragma unroll
        for (int k = 0; k < 9; k++) acc[k] = 0.f;
#pragma unroll 8
        for (int p = 0; p < 64; p++) {
            float pv = pix_s[p * 257 + c];
            float4 afa = *(const float4*)&aff_s[p * 12];
            float4 afb = *(const float4*)&aff_s[p * 12 + 4];
            float af8 = aff_s[p * 12 + 8];
            acc[0] += pv * afa.x; acc[1] += pv * afa.y;
            acc[2] += pv * afa.z; acc[3] += pv * afa.w;
            acc[4] += pv * afb.x; acc[5] += pv * afb.y;
            acc[6] += pv * afb.z; acc[7] += pv * afb.w;
            acc[8] += pv * af8;
        }
        float* Mo = g_M + (size_t)bt * 9 * Cc;
#pragma unroll
        for (int k = 0; k < 9; k++) Mo[k * Cc + c] = acc[k];
    }
}

// ------------------------------- K3: fold ----------------------------------
__global__ void k_fold() {
    int bt = blockIdx.x;
    int b = bt >> 8, t = bt & 255;
    int y = t >> 4, x = t & 15;
    __shared__ float s_as;
    int tid = threadIdx.x;
    if (tid == 0) {
        float s = 0.f;
        for (int ny = y - 1; ny <= y + 1; ny++)
            for (int nx = x - 1; nx <= x + 1; nx++)
                if ((unsigned)ny < GG && (unsigned)nx < GG) {
                    int k = (y - ny + 1) * 3 + (x - nx + 1);
                    s += g_asum[(b * NT + ny * GG + nx) * 9 + k];
                }
        s_as = s + 1e-12f;
    }
    __syncthreads();
    int c = tid;
    float s = 0.f;
    for (int ny = y - 1; ny <= y + 1; ny++)
        for (int nx = x - 1; nx <= x + 1; nx++)
            if ((unsigned)ny < GG && (unsigned)nx < GG) {
                int k = (y - ny + 1) * 3 + (x - nx + 1);
                s += g_M[((size_t)(b * NT + ny * GG + nx) * 9 + k) * Cc + c];
            }
    g_sf[bt * Cc + c] = s / s_as;
}

// --------------------------- GEMM (token-major out) -------------------------
// C[n][m] = sum_k A[m][k] * Bm[n][k];  K=256; tile 64x64, micro 4x4,
// k-major smem frags, double-buffered.
template <int MM>
__device__ __forceinline__ void gemm_tok(const float* __restrict__ A,
                                         const float* __restrict__ Bm,
                                         float* __restrict__ Cm) {
    const int K = 256;
    __shared__ float As[2][32 * 68];
    __shared__ float Bs[2][32 * 68];
    int bm = blockIdx.x * 64;
    int bn = blockIdx.y * 64;
    int tid = threadIdx.x;
    int txq = tid & 15, tyq = tid >> 4;

    float4 rA[2], rB[2];
    int f0 = tid, f1 = tid + 256;
    int r0 = f0 >> 3, k0q = (f0 & 7) * 4;
    int r1 = f1 >> 3, k1q = (f1 & 7) * 4;

    rA[0] = *(const float4*)(A + (size_t)(bm + r0) * K + k0q);
    rA[1] = *(const float4*)(A + (size_t)(bm + r1) * K + k1q);
    rB[0] = *(const float4*)(Bm + (size_t)(bn + r0) * K + k0q);
    rB[1] = *(const float4*)(Bm + (size_t)(bn + r1) * K + k1q);
    As[0][(k0q + 0) * 68 + r0] = rA[0].x; As[0][(k0q + 1) * 68 + r0] = rA[0].y;
    As[0][(k0q + 2) * 68 + r0] = rA[0].z; As[0][(k0q + 3) * 68 + r0] = rA[0].w;
    As[0][(k1q + 0) * 68 + r1] = rA[1].x; As[0][(k1q + 1) * 68 + r1] = rA[1].y;
    As[0][(k1q + 2) * 68 + r1] = rA[1].z; As[0][(k1q + 3) * 68 + r1] = rA[1].w;
    Bs[0][(k0q + 0) * 68 + r0] = rB[0].x; Bs[0][(k0q + 1) * 68 + r0] = rB[0].y;
    Bs[0][(k0q + 2) * 68 + r0] = rB[0].z; Bs[0][(k0q + 3) * 68 + r0] = rB[0].w;
    Bs[0][(k1q + 0) * 68 + r1] = rB[1].x; Bs[0][(k1q + 1) * 68 + r1] = rB[1].y;
    Bs[0][(k1q + 2) * 68 + r1] = rB[1].z; Bs[0][(k1q + 3) * 68 + r1] = rB[1].w;
    __syncthreads();

    float acc[4][4];
#pragma unroll
    for (int i = 0; i < 4; i++)
#pragma unroll
        for (int j = 0; j < 4; j++) acc[i][j] = 0.f;

#pragma unroll
    for (int tile = 0; tile < 8; tile++) {
        if (tile < 7) {
            int kb = (tile + 1) * 32;
            rA[0] = *(const float4*)(A + (size_t)(bm + r0) * K + kb + k0q);
            rA[1] = *(const float4*)(A + (size_t)(bm + r1) * K + kb + k1q);
            rB[0] = *(const float4*)(Bm + (size_t)(bn + r0) * K + kb + k0q);
            rB[1] = *(const float4*)(Bm + (size_t)(bn + r1) * K + kb + k1q);
        }
        int buf = tile & 1;
#pragma unroll
        for (int kk = 0; kk < 32; kk++) {
            float4 a = *(const float4*)&As[buf][kk * 68 + tyq * 4];
            float4 bb = *(const float4*)&Bs[buf][kk * 68 + txq * 4];
            acc[0][0] += a.x * bb.x; acc[0][1] += a.x * bb.y;
            acc[0][2] += a.x * bb.z; acc[0][3] += a.x * bb.w;
            acc[1][0] += a.y * bb.x; acc[1][1] += a.y * bb.y;
            acc[1][2] += a.y * bb.z; acc[1][3] += a.y * bb.w;
            acc[2][0] += a.z * bb.x; acc[2][1] += a.z * bb.y;
            acc[2][2] += a.z * bb.z; acc[2][3] += a.z * bb.w;
            acc[3][0] += a.w * bb.x; acc[3][1] += a.w * bb.y;
            acc[3][2] += a.w * bb.z; acc[3][3] += a.w * bb.w;
        }
        if (tile < 7) {
            int nb = (tile + 1) & 1;
            As[nb][(k0q + 0) * 68 + r0] = rA[0].x; As[nb][(k0q + 1) * 68 + r0] = rA[0].y;
            As[nb][(k0q + 2) * 68 + r0] = rA[0].z; As[nb][(k0q + 3) * 68 + r0] = rA[0].w;
            As[nb][(k1q + 0) * 68 + r1] = rA[1].x; As[nb][(k1q + 1) * 68 + r1] = rA[1].y;
            As[nb][(k1q + 2) * 68 + r1] = rA[1].z; As[nb][(k1q + 3) * 68 + r1] = rA[1].w;
            Bs[nb][(k0q + 0) * 68 + r0] = rB[0].x; Bs[nb][(k0q + 1) * 68 + r0] = rB[0].y;
            Bs[nb][(k0q + 2) * 68 + r0] = rB[0].z; Bs[nb][(k0q + 3) * 68 + r0] = rB[0].w;
            Bs[nb][(k1q + 0) * 68 + r1] = rB[1].x; Bs[nb][(k1q + 1) * 68 + r1] = rB[1].y;
            Bs[nb][(k1q + 2) * 68 + r1] = rB[1].z; Bs[nb][(k1q + 3) * 68 + r1] = rB[1].w;
            __syncthreads();
        }
    }
#pragma unroll
    for (int j = 0; j < 4; j++) {
        float4 v;
        v.x = acc[0][j]; v.y = acc[1][j]; v.z = acc[2][j]; v.w = acc[3][j];
        *(float4*)(Cm + (size_t)(bn + txq * 4 + j) * MM + bm + tyq * 4) = v;
    }
}

__global__ void k_gemm_qkv(const float* __restrict__ A) { gemm_tok<768>(A, g_sf, g_qkvt); }
__global__ void k_gemm_proj(const float* __restrict__ A) { gemm_tok<256>(A, g_tmp, g_sfa); }

// ------------------------------ K5: attention -------------------------------
// 256 blocks = b(8) x h(8) x qquarter(4); 128 threads = 64 queries x 2 d-halves.
// K/V staged [m][36]; chunk-8 online softmax; one shfl per score.
#define K5_KV   (256 * 36)
#define K5_SMEM ((2 * K5_KV + 9 * 32) * 4)

__global__ void k_attn(const float* __restrict__ w_pe) {
    extern __shared__ float sm5[];
    float* k_s = sm5;
    float* v_s = k_s + K5_KV;
    float* wpe = v_s + K5_KV;   // [k][d] 9x32

    int bx = blockIdx.x;
    int b = bx >> 5;
    int h = (bx >> 2) & 7;
    int qq = bx & 3;
    int tid = threadIdx.x;

    const float* base = g_qkvt + (size_t)b * NT * 768 + h * 96;
#pragma unroll
    for (int i = 0; i < 16; i++) {
        int f = tid + i * 128;
        int m = f >> 3, dq = (f & 7) * 4;
        float4 kv = *(const float4*)(base + (size_t)m * 768 + 32 + dq);
        float4 vv = *(const float4*)(base + (size_t)m * 768 + 64 + dq);
        *(float4*)&k_s[m * 36 + dq] = kv;
        *(float4*)&v_s[m * 36 + dq] = vv;
    }
    for (int idx = tid; idx < 288; idx += 128) {
        int d = idx & 31, k = idx >> 5;
        wpe[k * 32 + d] = w_pe[(h * 32 + d) * 9 + k];
    }
    __syncthreads();

    int j = qq * 64 + (tid >> 1);
    int dh = (tid & 1) * 16;
    float q[16];
#pragma unroll
    for (int i = 0; i < 4; i++) {
        float4 qv = *(const float4*)(base + (size_t)j * 768 + dh + i * 4);
        q[4 * i + 0] = qv.x * ATTN_SCALE; q[4 * i + 1] = qv.y * ATTN_SCALE;
        q[4 * i + 2] = qv.z * ATTN_SCALE; q[4 * i + 3] = qv.w * ATTN_SCALE;
    }

    float o[16];
#pragma unroll
    for (int d = 0; d < 16; d++) o[d] = 0.f;
    float mx = -1e30f, l = 0.f;

    for (int m0 = 0; m0 < 256; m0 += 8) {
        float sc[8];
        float cmax = -1e30f;
#pragma unroll
        for (int mm = 0; mm < 8; mm++) {
            const float* kr = k_s + (m0 + mm) * 36 + dh;
            float s = 0.f;
#pragma unroll
            for (int i = 0; i < 4; i++) {
                float4 kv = *(const float4*)(kr + 4 * i);
                s += q[4 * i + 0] * kv.x + q[4 * i + 1] * kv.y
                   + q[4 * i + 2] * kv.z + q[4 * i + 3] * kv.w;
            }
            s += __shfl_xor_sync(0xffffffffu, s, 1);
            sc[mm] = s;
            cmax = fmaxf(cmax, s);
        }
        float nm = fmaxf(mx, cmax);
        float corr = __expf(mx - nm);
        l *= corr;
#pragma unroll
        for (int d = 0; d < 16; d++) o[d] *= corr;
#pragma unroll
        for (int mm = 0; mm < 8; mm++) {
            float p = __expf(sc[mm] - nm);
            l += p;
            const float* vr = v_s + (m0 + mm) * 36 + dh;
#pragma unroll
            for (int i = 0; i < 4; i++) {
                float4 vv = *(const float4*)(vr + 4 * i);
                o[4 * i + 0] += p * vv.x; o[4 * i + 1] += p * vv.y;
                o[4 * i + 2] += p * vv.z; o[4 * i + 3] += p * vv.w;
            }
        }
        mx = nm;
    }
    float invl = 1.f / l;

    int y = j >> 4, xx = j & 15;
    float* outp = g_tmp + ((size_t)(b * NT + j)) * Cc + h * 32 + dh;
#pragma unroll
    for (int i = 0; i < 4; i++) {
        float pe0 = 0.f, pe1 = 0.f, pe2 = 0.f, pe3 = 0.f;
#pragma unroll
        for (int u = 0; u < 3; u++) {
            int ny = y + u - 1;
            if ((unsigned)ny >= GG) continue;
#pragma unroll
            for (int v = 0; v < 3; v++) {
                int nx = xx + v - 1;
                if ((unsigned)nx >= GG) continue;
                int k = u * 3 + v;
                float4 w4 = *(const float4*)&wpe[k * 32 + dh + 4 * i];
                float4 vv = *(const float4*)&v_s[(ny * 16 + nx) * 36 + dh + 4 * i];
                pe0 += w4.x * vv.x; pe1 += w4.y * vv.y;
                pe2 += w4.z * vv.z; pe3 += w4.w * vv.w;
            }
        }
        float4 r;
        r.x = o[4 * i + 0] * invl + pe0;
        r.y = o[4 * i + 1] * invl + pe1;
        r.z = o[4 * i + 2] * invl + pe2;
        r.w = o[4 * i + 3] * invl + pe3;
        *(float4*)(outp + 4 * i) = r;
    }
}

// ------------------------------ K7: scatter ---------------------------------
// out[c][s] = sum_k aff[c>>2][k] * sfa9[k][(c&3)*64 + s].
// Thread = (pg, cq, squad): caches s9[k][cq*64 + squad*4..+3] in 9 float4 regs,
// loops p over its 16-p group with broadcast aff loads; float4 coalesced stores.
__global__ void k_scatter(float* __restrict__ out) {
    __shared__ float s9[9 * 256];        // [k][c']
    __shared__ float aff_s[64 * 12];     // [p][k] padded
    int bt = blockIdx.x;
    int b = bt >> 8, t = bt & 255;
    int ty = t >> 4, tx = t & 15;
    int tid = threadIdx.x;

    for (int idx = tid; idx < 9 * 256; idx += 256) {
        int k = idx >> 8, c = idx & 255;
        int ny = ty + k / 3 - 1, nx = tx + k % 3 - 1;
        s9[idx] = ((unsigned)ny < GG && (unsigned)nx < GG)
                      ? g_sfa[(size_t)(b * NT + ny * GG + nx) * Cc + c]
                      : 0.f;
    }
    for (int idx = tid; idx < 576; idx += 256) {
        int p = idx / 9, k = idx - p * 9;
        aff_s[p * 12 + k] = g_aff[bt * 576 + idx];
    }
    __syncthreads();

    int squad = tid & 15;          // 4 consecutive s values
    int cq = (tid >> 4) & 3;       // c & 3
    int pg = tid >> 6;             // 16-p group

    float4 rk[9];
#pragma unroll
    for (int k = 0; k < 9; k++)
        rk[k] = *(const float4*)&s9[k * 256 + cq * 64 + squad * 4];

    int sy = squad >> 1, sxb = (squad & 1) * 4;
    float* opb = out + (size_t)b * Cc * HW + (ty * 8 + sy) * 128 + tx * 8 + sxb;

#pragma unroll
    for (int i = 0; i < 16; i++) {
        int p = pg * 16 + i;
        float4 afa = *(const float4*)&aff_s[p * 12];
        float4 afb = *(const float4*)&aff_s[p * 12 + 4];
        float af8 = aff_s[p * 12 + 8];
        float4 acc;
        acc.x = afa.x * rk[0].x; acc.y = afa.x * rk[0].y;
        acc.z = afa.x * rk[0].z; acc.w = afa.x * rk[0].w;
        acc.x += afa.y * rk[1].x; acc.y += afa.y * rk[1].y;
        acc.z += afa.y * rk[1].z; acc.w += afa.y * rk[1].w;
        acc.x += afa.z * rk[2].x; acc.y += afa.z * rk[2].y;
        acc.z += afa.z * rk[2].z; acc.w += afa.z * rk[2].w;
        acc.x += afa.w * rk[3].x; acc.y += afa.w * rk[3].y;
        acc.z += afa.w * rk[3].z; acc.w += afa.w * rk[3].w;
        acc.x += afb.x * rk[4].x; acc.y += afb.x * rk[4].y;
        acc.z += afb.x * rk[4].z; acc.w += afb.x * rk[4].w;
        acc.x += afb.y * rk[5].x; acc.y += afb.y * rk[5].y;
        acc.z += afb.y * rk[5].z; acc.w += afb.y * rk[5].w;
        acc.x += afb.z * rk[6].x; acc.y += afb.z * rk[6].y;
        acc.z += afb.z * rk[6].z; acc.w += afb.z * rk[6].w;
        acc.x += afb.w * rk[7].x; acc.y += afb.w * rk[7].y;
        acc.z += afb.w * rk[7].z; acc.w += afb.w * rk[7].w;
        acc.x += af8 * rk[8].x; acc.y += af8 * rk[8].y;
        acc.z += af8 * rk[8].z; acc.w += af8 * rk[8].w;
        int c = p * 4 + cq;
        *(float4*)(opb + (size_t)c * HW) = acc;
    }
}

// ------------------------------- launcher -----------------------------------
extern "C" void kernel_launch(void* const* d_in, const int* in_sizes, int n_in,
                              void* d_out, int out_size) {
    (void)in_sizes; (void)n_in; (void)out_size;
    const float* x      = (const float*)d_in[0];
    const float* w_qkv  = (const float*)d_in[1];
    const float* w_pe   = (const float*)d_in[2];
    const float* w_proj = (const float*)d_in[3];
    float* out = (float*)d_out;

    cudaFuncSetAttribute(k_aff, cudaFuncAttributeMaxDynamicSharedMemorySize, K2_SMEM);
    cudaFuncSetAttribute(k_attn, cudaFuncAttributeMaxDynamicSharedMemorySize, K5_SMEM);

    k_pool<<<NTOK, 256>>>(x);
    k_aff<<<NTOK, 256, K2_SMEM>>>(x);
    k_fold<<<NTOK, 256>>>();
    k_gemm_qkv<<<dim3(12, 32), 256>>>(w_qkv);
    k_attn<<<256, 128, K5_SMEM>>>(w_pe);
    k_gemm_proj<<<dim3(4, 32), 256>>>(w_proj);
    k_scatter<<<NTOK, 256>>>(out);
}